// round 4
// baseline (speedup 1.0000x reference)
#include <cuda_runtime.h>
#include <math.h>

#define BB 1024
#define FEA 4096
#define HH 1024
#define TT 64
#define GAP 16

// Scratch (device globals — no allocation allowed)
__device__ float g_x1[BB * HH];
__device__ float g_xlow[BB * HH];
__device__ float g_u[BB * HH];
__device__ float g_hx[2][BB * HH];
__device__ float g_Wsum[HH * HH];
__device__ float g_bias[HH];

// Epilogue modes
#define M_RELU_BIAS 0   // relu(acc + bias[c])
#define M_ADD_BIAS  1   // acc + bias[c]
#define M_TANH_ADDC 2   // tanh(acc + Cadd[r, c])
#define M_TANH_BIAS 3   // tanh(acc + bias[c])

// C[M=1024, N=1024] = A[M,K] * W[N,K]^T, row-major, with fused epilogue.
// BM=128, BN=64, BK=8, 256 threads, 8x4 per thread. Grid: (N/64, M/128) = (16, 8).
template <int MODE>
__global__ __launch_bounds__(256) void gemm_kernel(
    const float* __restrict__ A, const float* __restrict__ W,
    const float* __restrict__ Cadd, const float* __restrict__ bias,
    float* __restrict__ Cout, int K)
{
    __shared__ float As[8][128];
    __shared__ float Bs[8][64];

    const int t  = threadIdx.x;
    const int tx = t & 15;        // N direction (0..15), 4 cols each
    const int ty = t >> 4;        // M direction (0..15), 8 rows each
    const int bm = blockIdx.y * 128;
    const int bn = blockIdx.x * 64;

    float acc[8][4];
#pragma unroll
    for (int i = 0; i < 8; i++)
#pragma unroll
        for (int j = 0; j < 4; j++) acc[i][j] = 0.f;

    const int aRow = t >> 1, aSeg = t & 1;          // 128 rows x 2 float4 segs
    const int bRow = t >> 1, bSeg = t & 1;          // threads < 128: 64 rows x 2 segs

    for (int k0 = 0; k0 < K; k0 += 8) {
        float4 av = *(const float4*)&A[(size_t)(bm + aRow) * K + k0 + aSeg * 4];
        As[aSeg * 4 + 0][aRow] = av.x;
        As[aSeg * 4 + 1][aRow] = av.y;
        As[aSeg * 4 + 2][aRow] = av.z;
        As[aSeg * 4 + 3][aRow] = av.w;
        if (t < 128) {
            float4 bv = *(const float4*)&W[(size_t)(bn + bRow) * K + k0 + bSeg * 4];
            Bs[bSeg * 4 + 0][bRow] = bv.x;
            Bs[bSeg * 4 + 1][bRow] = bv.y;
            Bs[bSeg * 4 + 2][bRow] = bv.z;
            Bs[bSeg * 4 + 3][bRow] = bv.w;
        }
        __syncthreads();
#pragma unroll
        for (int k = 0; k < 8; k++) {
            float a[8], b[4];
#pragma unroll
            for (int i = 0; i < 8; i++) a[i] = As[k][ty * 8 + i];
#pragma unroll
            for (int j = 0; j < 4; j++) b[j] = Bs[k][tx * 4 + j];
#pragma unroll
            for (int i = 0; i < 8; i++)
#pragma unroll
                for (int j = 0; j < 4; j++) acc[i][j] = fmaf(a[i], b[j], acc[i][j]);
        }
        __syncthreads();
    }

#pragma unroll
    for (int i = 0; i < 8; i++) {
        const int r = bm + ty * 8 + i;
#pragma unroll
        for (int j = 0; j < 4; j++) {
            const int c = bn + tx * 4 + j;
            float v = acc[i][j];
            if (MODE == M_RELU_BIAS) v = fmaxf(v + bias[c], 0.f);
            else if (MODE == M_ADD_BIAS)  v = v + bias[c];
            else if (MODE == M_TANH_ADDC) v = tanhf(v + Cadd[(size_t)r * HH + c]);
            else /* M_TANH_BIAS */        v = tanhf(v + bias[c]);
            Cout[(size_t)r * HH + c] = v;
        }
    }
}

// probs[row] = sigmoid(dot(hx[row,:], Wa) + ba). One warp per row.
__global__ __launch_bounds__(256) void prob_kernel(
    const float* __restrict__ hx, const float* __restrict__ Wa,
    const float* __restrict__ ba, float* __restrict__ out)
{
    const int warp = threadIdx.x >> 5, lane = threadIdx.x & 31;
    const int row = blockIdx.x * 8 + warp;
    float s = 0.f;
#pragma unroll 8
    for (int k = lane; k < HH; k += 32)
        s = fmaf(hx[(size_t)row * HH + k], Wa[k], s);
#pragma unroll
    for (int o = 16; o; o >>= 1) s += __shfl_xor_sync(0xffffffffu, s, o);
    if (lane == 0) out[row] = 1.f / (1.f + expf(-(s + ba[0])));
}

// Wsum = Wih + Whh ; bias = bih + bhh
__global__ void prep_kernel(const float* __restrict__ Wih, const float* __restrict__ Whh,
                            const float* __restrict__ bih, const float* __restrict__ bhh)
{
    const int i = blockIdx.x * blockDim.x + threadIdx.x;
    if (i < HH * HH) g_Wsum[i] = Wih[i] + Whh[i];
    if (i < HH)      g_bias[i] = bih[i] + bhh[i];
}

extern "C" void kernel_launch(void* const* d_in, const int* in_sizes, int n_in,
                              void* d_out, int out_size)
{
    const float* inputs = (const float*)d_in[0];
    const float* W1  = (const float*)d_in[1];
    const float* b1  = (const float*)d_in[2];
    const float* W2  = (const float*)d_in[3];
    const float* b2  = (const float*)d_in[4];
    const float* Wih = (const float*)d_in[5];
    const float* Whh = (const float*)d_in[6];
    const float* bih = (const float*)d_in[7];
    const float* bhh = (const float*)d_in[8];
    const float* Wa  = (const float*)d_in[9];
    const float* ba  = (const float*)d_in[10];
    float* out = (float*)d_out;

    float *x1, *xlow, *u, *hxbase, *Wsum, *biasv;
    cudaGetSymbolAddress((void**)&x1,     g_x1);
    cudaGetSymbolAddress((void**)&xlow,   g_xlow);
    cudaGetSymbolAddress((void**)&u,      g_u);
    cudaGetSymbolAddress((void**)&hxbase, g_hx);
    cudaGetSymbolAddress((void**)&Wsum,   g_Wsum);
    cudaGetSymbolAddress((void**)&biasv,  g_bias);
    float* hx0 = hxbase;
    float* hx1 = hxbase + (size_t)BB * HH;

    dim3 grid(HH / 64, BB / 128);  // (16, 8)

    // low_fc
    gemm_kernel<M_RELU_BIAS><<<grid, 256>>>(inputs, W1, nullptr, b1, x1, FEA);
    gemm_kernel<M_RELU_BIAS><<<grid, 256>>>(x1, W2, nullptr, b2, xlow, HH);

    // Wsum = Wih+Whh, bias = bih+bhh
    prep_kernel<<<(HH * HH + 255) / 256, 256>>>(Wih, Whh, bih, bhh);

    // u = x_low @ Wih^T + bias  (loop-invariant input-feed contribution)
    gemm_kernel<M_ADD_BIAS><<<grid, 256>>>(xlow, Wih, nullptr, biasv, u, HH);

    // hx <- x_low
    cudaMemcpyAsync(hx0, xlow, (size_t)BB * HH * sizeof(float),
                    cudaMemcpyDeviceToDevice);

    float* cur = hx0;
    float* nxt = hx1;
    for (int t = 0; t < TT; t++) {
        if ((t % GAP) == 0) {
            // hx_new = tanh(u + hx @ Whh^T)
            gemm_kernel<M_TANH_ADDC><<<grid, 256>>>(cur, Whh, u, nullptr, nxt, HH);
        } else {
            // hx_new = tanh(hx @ (Wih+Whh)^T + bias)
            gemm_kernel<M_TANH_BIAS><<<grid, 256>>>(cur, Wsum, nullptr, biasv, nxt, HH);
        }
        prob_kernel<<<BB / 8, 256>>>(nxt, Wa, ba, out + (size_t)t * BB);
        float* tmp = cur; cur = nxt; nxt = tmp;
    }

    // final hx
    cudaMemcpyAsync(out + (size_t)TT * BB, cur, (size_t)BB * HH * sizeof(float),
                    cudaMemcpyDeviceToDevice);
}

// round 6
// speedup vs baseline: 2.1625x; 2.1625x over previous
#include <cuda_runtime.h>
#include <cuda_bf16.h>
#include <stdint.h>
#include <math.h>

#define BB 1024
#define FEA 4096
#define HH 1024
#define TT 64
#define GAP 16

#define BM 128
#define BN 64
#define BK 32
#define LDSW 40   // padded smem leading dim (bf16 elems): conflict-free for ldmatrix

typedef __nv_bfloat16 bf16;

// ---------------- scratch (device globals; no allocation allowed) ----------------
__device__ float g_x1[BB * HH];
__device__ float g_xlow[BB * HH];
__device__ float g_u[BB * HH];
__device__ float g_hx[2][BB * HH];
__device__ float g_bias[HH];

__device__ bf16 g_W1h[HH * FEA], g_W1l[HH * FEA];
__device__ bf16 g_W2h[HH * HH],  g_W2l[HH * HH];
__device__ bf16 g_Wihh[HH * HH], g_Wihl[HH * HH];
__device__ bf16 g_Whhh[HH * HH], g_Whhl[HH * HH];
__device__ bf16 g_Wsh[HH * HH],  g_Wsl[HH * HH];

// Epilogue modes
#define M_RELU_BIAS 0
#define M_ADD_BIAS  1
#define M_TANH_ADDC 2
#define M_TANH_BIAS 3

// ---------------- PTX helpers ----------------
__device__ __forceinline__ unsigned smem_u32(const void* p) {
    unsigned addr;
    asm("{ .reg .u64 tmp; cvta.to.shared.u64 tmp, %1; cvt.u32.u64 %0, tmp; }"
        : "=r"(addr) : "l"(p));
    return addr;
}

__device__ __forceinline__ void ldm4(unsigned* r, const bf16* p) {
    unsigned a = smem_u32(p);
    asm volatile("ldmatrix.sync.aligned.m8n8.x4.shared.b16 {%0,%1,%2,%3}, [%4];"
                 : "=r"(r[0]), "=r"(r[1]), "=r"(r[2]), "=r"(r[3]) : "r"(a));
}

__device__ __forceinline__ void mma_bf16(float* c, const unsigned* a, const unsigned* b) {
    asm volatile("mma.sync.aligned.m16n8k16.row.col.f32.bf16.bf16.f32 "
                 "{%0,%1,%2,%3},{%4,%5,%6,%7},{%8,%9},{%0,%1,%2,%3};"
                 : "+f"(c[0]), "+f"(c[1]), "+f"(c[2]), "+f"(c[3])
                 : "r"(a[0]), "r"(a[1]), "r"(a[2]), "r"(a[3]), "r"(b[0]), "r"(b[1]));
}

// ---------------- weight split prep ----------------
__global__ void split_kernel(const float* __restrict__ src, bf16* __restrict__ hi,
                             bf16* __restrict__ lo, int n)
{
    int i = blockIdx.x * blockDim.x + threadIdx.x;
    if (i < n) {
        float x = src[i];
        bf16 h = __float2bfloat16_rn(x);
        hi[i] = h;
        lo[i] = __float2bfloat16_rn(x - __bfloat162float(h));
    }
}

__global__ void sumsplit_kernel(const float* __restrict__ a, const float* __restrict__ b,
                                bf16* __restrict__ hi, bf16* __restrict__ lo,
                                const float* __restrict__ bih, const float* __restrict__ bhh,
                                int n)
{
    int i = blockIdx.x * blockDim.x + threadIdx.x;
    if (i < n) {
        float x = a[i] + b[i];
        bf16 h = __float2bfloat16_rn(x);
        hi[i] = h;
        lo[i] = __float2bfloat16_rn(x - __bfloat162float(h));
    }
    if (i < HH) g_bias[i] = bih[i] + bhh[i];
}

// ---------------- tensor-core GEMM: C[M,1024] = A[M,K] @ W[1024,K]^T (+ epilogue) ----------------
// A fp32 (split to hi/lo bf16 on the fly), W pre-split hi/lo bf16.
// acc += Ah*Wh + Ah*Wl + Al*Wh  (fp32 accumulate; lo*lo ~2^-16 dropped)
// BM=128, BN=64, BK=32, 256 threads (8 warps, 4x2), grid (N/64, M/128).
template <int MODE>
__global__ __launch_bounds__(256) void gemm_tc(
    const float* __restrict__ A, const bf16* __restrict__ Wh, const bf16* __restrict__ Wl,
    const float* __restrict__ Cadd, const float* __restrict__ bias,
    float* __restrict__ Cout, int K)
{
    __shared__ bf16 sAh[BM * LDSW], sAl[BM * LDSW];
    __shared__ bf16 sWh[BN * LDSW], sWl[BN * LDSW];

    const int t = threadIdx.x;
    const int lane = t & 31, wid = t >> 5;
    const int bm = blockIdx.y * BM, bn = blockIdx.x * BN;
    const int wm = (wid >> 1) * 32;   // warp row offset (0,32,64,96)
    const int wn = (wid & 1) * 32;    // warp col offset (0,32)

    float acc[2][4][4];
#pragma unroll
    for (int i = 0; i < 2; i++)
#pragma unroll
        for (int j = 0; j < 4; j++)
#pragma unroll
            for (int q = 0; q < 4; q++) acc[i][j][q] = 0.f;

    const int arow = t >> 1, aseg = (t & 1) * 16;   // A: 128 rows x 2 segs of 16 floats
    const int wrow = t >> 2, wch = (t & 3) * 8;     // W: 64 rows x 4 chunks of 8 bf16

    for (int k0 = 0; k0 < K; k0 += BK) {
        // ---- stage A tile (fp32 -> hi/lo bf16), stores as packed pairs ----
        {
            const float* ap = A + (size_t)(bm + arow) * K + k0 + aseg;
            unsigned* dh = (unsigned*)&sAh[arow * LDSW + aseg];
            unsigned* dl = (unsigned*)&sAl[arow * LDSW + aseg];
#pragma unroll
            for (int q = 0; q < 4; q++) {
                float4 f = *(const float4*)(ap + q * 4);
                float v[4] = {f.x, f.y, f.z, f.w};
                bf16 h0 = __float2bfloat16_rn(v[0]);
                bf16 h1 = __float2bfloat16_rn(v[1]);
                bf16 h2 = __float2bfloat16_rn(v[2]);
                bf16 h3 = __float2bfloat16_rn(v[3]);
                bf16 l0 = __float2bfloat16_rn(v[0] - __bfloat162float(h0));
                bf16 l1 = __float2bfloat16_rn(v[1] - __bfloat162float(h1));
                bf16 l2 = __float2bfloat16_rn(v[2] - __bfloat162float(h2));
                bf16 l3 = __float2bfloat16_rn(v[3] - __bfloat162float(h3));
                __nv_bfloat162 ph0 = __halves2bfloat162(h0, h1);
                __nv_bfloat162 ph1 = __halves2bfloat162(h2, h3);
                __nv_bfloat162 pl0 = __halves2bfloat162(l0, l1);
                __nv_bfloat162 pl1 = __halves2bfloat162(l2, l3);
                dh[q * 2 + 0] = *(unsigned*)&ph0;
                dh[q * 2 + 1] = *(unsigned*)&ph1;
                dl[q * 2 + 0] = *(unsigned*)&pl0;
                dl[q * 2 + 1] = *(unsigned*)&pl1;
            }
        }
        // ---- stage W tile (pre-split bf16) ----
        {
            *(uint4*)&sWh[wrow * LDSW + wch] =
                *(const uint4*)(Wh + (size_t)(bn + wrow) * K + k0 + wch);
            *(uint4*)&sWl[wrow * LDSW + wch] =
                *(const uint4*)(Wl + (size_t)(bn + wrow) * K + k0 + wch);
        }
        __syncthreads();

#pragma unroll
        for (int kk = 0; kk < BK; kk += 16) {
            unsigned ah[2][4], al[2][4], bh[4][2], bl[4][2];
            // A frags: m16k16, ldmatrix.x4
#pragma unroll
            for (int i = 0; i < 2; i++) {
                int r = wm + i * 16 + (lane & 15);
                int c = kk + (lane >> 4) * 8;
                ldm4(ah[i], &sAh[r * LDSW + c]);
                ldm4(al[i], &sAl[r * LDSW + c]);
            }
            // B frags: each x4 yields two n8k16 operands
#pragma unroll
            for (int jj = 0; jj < 2; jj++) {
                int r = wn + jj * 16 + ((lane >> 4) << 3) + (lane & 7);
                int c = kk + ((lane >> 3) & 1) * 8;
                unsigned tmp[4];
                ldm4(tmp, &sWh[r * LDSW + c]);
                bh[2 * jj][0] = tmp[0]; bh[2 * jj][1] = tmp[1];
                bh[2 * jj + 1][0] = tmp[2]; bh[2 * jj + 1][1] = tmp[3];
                ldm4(tmp, &sWl[r * LDSW + c]);
                bl[2 * jj][0] = tmp[0]; bl[2 * jj][1] = tmp[1];
                bl[2 * jj + 1][0] = tmp[2]; bl[2 * jj + 1][1] = tmp[3];
            }
#pragma unroll
            for (int i = 0; i < 2; i++)
#pragma unroll
                for (int j = 0; j < 4; j++) {
                    mma_bf16(acc[i][j], ah[i], bh[j]);
                    mma_bf16(acc[i][j], ah[i], bl[j]);
                    mma_bf16(acc[i][j], al[i], bh[j]);
                }
        }
        __syncthreads();
    }

    // ---- epilogue ----
    const int g = lane >> 2, tg = lane & 3;
#pragma unroll
    for (int i = 0; i < 2; i++) {
#pragma unroll
        for (int j = 0; j < 4; j++) {
            int c0 = bn + wn + j * 8 + tg * 2;
#pragma unroll
            for (int h = 0; h < 2; h++) {
                int r = bm + wm + i * 16 + g + h * 8;
                float v0 = acc[i][j][h * 2 + 0];
                float v1 = acc[i][j][h * 2 + 1];
                if (MODE == M_RELU_BIAS) {
                    v0 = fmaxf(v0 + bias[c0], 0.f);
                    v1 = fmaxf(v1 + bias[c0 + 1], 0.f);
                } else if (MODE == M_ADD_BIAS) {
                    v0 += bias[c0];
                    v1 += bias[c0 + 1];
                } else if (MODE == M_TANH_ADDC) {
                    v0 = tanhf(v0 + Cadd[(size_t)r * HH + c0]);
                    v1 = tanhf(v1 + Cadd[(size_t)r * HH + c0 + 1]);
                } else { // M_TANH_BIAS
                    v0 = tanhf(v0 + bias[c0]);
                    v1 = tanhf(v1 + bias[c0 + 1]);
                }
                Cout[(size_t)r * HH + c0]     = v0;
                Cout[(size_t)r * HH + c0 + 1] = v1;
            }
        }
    }
}

// probs[row] = sigmoid(dot(hx[row,:], Wa) + ba). One warp per row.
__global__ __launch_bounds__(256) void prob_kernel(
    const float* __restrict__ hx, const float* __restrict__ Wa,
    const float* __restrict__ ba, float* __restrict__ out)
{
    const int warp = threadIdx.x >> 5, lane = threadIdx.x & 31;
    const int row = blockIdx.x * 8 + warp;
    float s = 0.f;
#pragma unroll 8
    for (int k = lane; k < HH; k += 32)
        s = fmaf(hx[(size_t)row * HH + k], Wa[k], s);
#pragma unroll
    for (int o = 16; o; o >>= 1) s += __shfl_xor_sync(0xffffffffu, s, o);
    if (lane == 0) out[row] = 1.f / (1.f + expf(-(s + ba[0])));
}

// ---------------- launch ----------------
extern "C" void kernel_launch(void* const* d_in, const int* in_sizes, int n_in,
                              void* d_out, int out_size)
{
    const float* inputs = (const float*)d_in[0];
    const float* W1  = (const float*)d_in[1];
    const float* b1  = (const float*)d_in[2];
    const float* W2  = (const float*)d_in[3];
    const float* b2  = (const float*)d_in[4];
    const float* Wih = (const float*)d_in[5];
    const float* Whh = (const float*)d_in[6];
    const float* bih = (const float*)d_in[7];
    const float* bhh = (const float*)d_in[8];
    const float* Wa  = (const float*)d_in[9];
    const float* ba  = (const float*)d_in[10];
    float* out = (float*)d_out;

    float *x1, *xlow, *u, *hxbase, *biasv;
    bf16 *W1h, *W1l, *W2h, *W2l, *Wihh, *Wihl, *Whhh, *Whhl, *Wsh, *Wsl;
    cudaGetSymbolAddress((void**)&x1,     g_x1);
    cudaGetSymbolAddress((void**)&xlow,   g_xlow);
    cudaGetSymbolAddress((void**)&u,      g_u);
    cudaGetSymbolAddress((void**)&hxbase, g_hx);
    cudaGetSymbolAddress((void**)&biasv,  g_bias);
    cudaGetSymbolAddress((void**)&W1h,  g_W1h);  cudaGetSymbolAddress((void**)&W1l,  g_W1l);
    cudaGetSymbolAddress((void**)&W2h,  g_W2h);  cudaGetSymbolAddress((void**)&W2l,  g_W2l);
    cudaGetSymbolAddress((void**)&Wihh, g_Wihh); cudaGetSymbolAddress((void**)&Wihl, g_Wihl);
    cudaGetSymbolAddress((void**)&Whhh, g_Whhh); cudaGetSymbolAddress((void**)&Whhl, g_Whhl);
    cudaGetSymbolAddress((void**)&Wsh,  g_Wsh);  cudaGetSymbolAddress((void**)&Wsl,  g_Wsl);

    float* hx0 = hxbase;
    float* hx1 = hxbase + (size_t)BB * HH;

    // weight splits
    split_kernel<<<(HH * FEA + 255) / 256, 256>>>(W1, W1h, W1l, HH * FEA);
    split_kernel<<<(HH * HH + 255) / 256, 256>>>(W2, W2h, W2l, HH * HH);
    split_kernel<<<(HH * HH + 255) / 256, 256>>>(Wih, Wihh, Wihl, HH * HH);
    split_kernel<<<(HH * HH + 255) / 256, 256>>>(Whh, Whhh, Whhl, HH * HH);
    sumsplit_kernel<<<(HH * HH + 255) / 256, 256>>>(Wih, Whh, Wsh, Wsl, bih, bhh, HH * HH);

    dim3 grid(HH / BN, BB / BM);  // (16, 8)

    // low_fc
    gemm_tc<M_RELU_BIAS><<<grid, 256>>>(inputs, W1h, W1l, (const float*)0, b1, x1, FEA);
    gemm_tc<M_RELU_BIAS><<<grid, 256>>>(x1, W2h, W2l, (const float*)0, b2, xlow, HH);

    // u = x_low @ Wih^T + (bih + bhh)
    gemm_tc<M_ADD_BIAS><<<grid, 256>>>(xlow, Wihh, Wihl, (const float*)0, biasv, u, HH);

    // hx <- x_low
    cudaMemcpyAsync(hx0, xlow, (size_t)BB * HH * sizeof(float),
                    cudaMemcpyDeviceToDevice);

    float* cur = hx0;
    float* nxt = hx1;
    for (int t = 0; t < TT; t++) {
        if ((t % GAP) == 0) {
            // hx_new = tanh(u + hx @ Whh^T)
            gemm_tc<M_TANH_ADDC><<<grid, 256>>>(cur, Whhh, Whhl, u, (const float*)0, nxt, HH);
        } else {
            // hx_new = tanh(hx @ (Wih+Whh)^T + bias)
            gemm_tc<M_TANH_BIAS><<<grid, 256>>>(cur, Wsh, Wsl, (const float*)0, biasv, nxt, HH);
        }
        prob_kernel<<<BB / 8, 256>>>(nxt, Wa, ba, out + (size_t)t * BB);
        float* tmp = cur; cur = nxt; nxt = tmp;
    }

    // final hx
    cudaMemcpyAsync(out + (size_t)TT * BB, cur, (size_t)BB * HH * sizeof(float),
                    cudaMemcpyDeviceToDevice);
}

// round 7
// speedup vs baseline: 2.8409x; 1.3137x over previous
#include <cuda_runtime.h>
#include <cuda_bf16.h>
#include <stdint.h>
#include <math.h>

#define BB 1024
#define FEA 4096
#define HH 1024
#define TT 64
#define GAP 16

#define BM 128
#define BN 64
#define BK 32
#define LDSW 40   // padded smem leading dim (bf16): conflict-free for ldmatrix

typedef __nv_bfloat16 bf16;

// ---------------- scratch (device globals; no allocation allowed) ----------------
__device__ float g_u[BB * HH];
__device__ float g_bias[HH];

__device__ bf16 g_Ih[BB * FEA],  g_Il[BB * FEA];     // split inputs
__device__ bf16 g_x1h[BB * HH],  g_x1l[BB * HH];     // layer1 out (split)
__device__ bf16 g_W1h[HH * FEA], g_W1l[HH * FEA];
__device__ bf16 g_W2h[HH * HH],  g_W2l[HH * HH];
__device__ bf16 g_Wihh[HH * HH], g_Wihl[HH * HH];
__device__ bf16 g_Whhh[HH * HH], g_Whhl[HH * HH];
__device__ bf16 g_Wsh[HH * HH],  g_Wsl[HH * HH];

// hx history, split: slot 0 = x_low, slot t+1 = hx after step t
__device__ bf16 g_hxh[(TT + 1) * (size_t)BB * HH];
__device__ bf16 g_hxl[(TT + 1) * (size_t)BB * HH];

// Epilogue modes
#define M_RELU_BIAS 0
#define M_ADD_BIAS  1
#define M_TANH_ADDC 2
#define M_TANH_BIAS 3

// ---------------- PTX helpers ----------------
__device__ __forceinline__ unsigned smem_u32(const void* p) {
    unsigned addr;
    asm("{ .reg .u64 tmp; cvta.to.shared.u64 tmp, %1; cvt.u32.u64 %0, tmp; }"
        : "=r"(addr) : "l"(p));
    return addr;
}

__device__ __forceinline__ void ldm4(unsigned* r, const bf16* p) {
    unsigned a = smem_u32(p);
    asm volatile("ldmatrix.sync.aligned.m8n8.x4.shared.b16 {%0,%1,%2,%3}, [%4];"
                 : "=r"(r[0]), "=r"(r[1]), "=r"(r[2]), "=r"(r[3]) : "r"(a));
}

__device__ __forceinline__ void mma_bf16(float* c, const unsigned* a, const unsigned* b) {
    asm volatile("mma.sync.aligned.m16n8k16.row.col.f32.bf16.bf16.f32 "
                 "{%0,%1,%2,%3},{%4,%5,%6,%7},{%8,%9},{%0,%1,%2,%3};"
                 : "+f"(c[0]), "+f"(c[1]), "+f"(c[2]), "+f"(c[3])
                 : "r"(a[0]), "r"(a[1]), "r"(a[2]), "r"(a[3]), "r"(b[0]), "r"(b[1]));
}

// ---------------- prep kernels ----------------
__global__ void split_kernel(const float* __restrict__ src, bf16* __restrict__ hi,
                             bf16* __restrict__ lo, int n)
{
    int i = blockIdx.x * blockDim.x + threadIdx.x;
    if (i < n) {
        float x = src[i];
        bf16 h = __float2bfloat16_rn(x);
        hi[i] = h;
        lo[i] = __float2bfloat16_rn(x - __bfloat162float(h));
    }
}

__global__ void sumsplit_kernel(const float* __restrict__ a, const float* __restrict__ b,
                                bf16* __restrict__ hi, bf16* __restrict__ lo,
                                const float* __restrict__ bih, const float* __restrict__ bhh,
                                int n)
{
    int i = blockIdx.x * blockDim.x + threadIdx.x;
    if (i < n) {
        float x = a[i] + b[i];
        bf16 h = __float2bfloat16_rn(x);
        hi[i] = h;
        lo[i] = __float2bfloat16_rn(x - __bfloat162float(h));
    }
    if (i < HH) g_bias[i] = bih[i] + bhh[i];
}

// ---------------- tensor-core GEMM ----------------
// C[M,1024] = (Ah+Al)[M,K] @ (Wh+Wl)[1024,K]^T, epilogue MODE, output either
// fp32 (Cout) or split bf16 pair (Oh, Ol).
// acc += Ah*Wh + Ah*Wl + Al*Wh  (fp32 accumulate)
// BM=128, BN=64, BK=32, 256 threads (8 warps 4x2), grid (N/64, M/128).
template <int MODE, int OUT_SPLIT>
__global__ __launch_bounds__(256) void gemm_tc(
    const bf16* __restrict__ Ah, const bf16* __restrict__ Al,
    const bf16* __restrict__ Wh, const bf16* __restrict__ Wl,
    const float* __restrict__ Cadd, const float* __restrict__ bias,
    float* __restrict__ Cout, bf16* __restrict__ Oh, bf16* __restrict__ Ol,
    int K)
{
    __shared__ bf16 sAh[BM * LDSW], sAl[BM * LDSW];
    __shared__ bf16 sWh[BN * LDSW], sWl[BN * LDSW];

    const int t = threadIdx.x;
    const int lane = t & 31, wid = t >> 5;
    const int bm = blockIdx.y * BM, bn = blockIdx.x * BN;
    const int wm = (wid >> 1) * 32;
    const int wn = (wid & 1) * 32;

    float acc[2][4][4];
#pragma unroll
    for (int i = 0; i < 2; i++)
#pragma unroll
        for (int j = 0; j < 4; j++)
#pragma unroll
            for (int q = 0; q < 4; q++) acc[i][j][q] = 0.f;

    const int arow = t >> 1, aseg = (t & 1) * 16;   // A: 128 rows x 2 segs of 16 bf16
    const int wrow = t >> 2, wch = (t & 3) * 8;     // W: 64 rows x 4 chunks of 8 bf16

    const bf16* pAh = Ah + (size_t)(bm + arow) * K + aseg;
    const bf16* pAl = Al + (size_t)(bm + arow) * K + aseg;
    const bf16* pWh = Wh + (size_t)(bn + wrow) * K + wch;
    const bf16* pWl = Wl + (size_t)(bn + wrow) * K + wch;

    // register prefetch of tile k0=0
    uint4 rah0 = *(const uint4*)(pAh);
    uint4 rah1 = *(const uint4*)(pAh + 8);
    uint4 ral0 = *(const uint4*)(pAl);
    uint4 ral1 = *(const uint4*)(pAl + 8);
    uint4 rwh  = *(const uint4*)(pWh);
    uint4 rwl  = *(const uint4*)(pWl);

    for (int k0 = 0; k0 < K; k0 += BK) {
        // ---- commit prefetched regs to smem ----
        *(uint4*)&sAh[arow * LDSW + aseg]     = rah0;
        *(uint4*)&sAh[arow * LDSW + aseg + 8] = rah1;
        *(uint4*)&sAl[arow * LDSW + aseg]     = ral0;
        *(uint4*)&sAl[arow * LDSW + aseg + 8] = ral1;
        *(uint4*)&sWh[wrow * LDSW + wch] = rwh;
        *(uint4*)&sWl[wrow * LDSW + wch] = rwl;
        __syncthreads();

        // ---- prefetch next tile (overlaps with MMA below) ----
        if (k0 + BK < K) {
            const int kn = k0 + BK;
            rah0 = *(const uint4*)(pAh + kn);
            rah1 = *(const uint4*)(pAh + kn + 8);
            ral0 = *(const uint4*)(pAl + kn);
            ral1 = *(const uint4*)(pAl + kn + 8);
            rwh  = *(const uint4*)(pWh + kn);
            rwl  = *(const uint4*)(pWl + kn);
        }

#pragma unroll
        for (int kk = 0; kk < BK; kk += 16) {
            unsigned ah[2][4], al[2][4], bh[4][2], bl[4][2];
#pragma unroll
            for (int i = 0; i < 2; i++) {
                int r = wm + i * 16 + (lane & 15);
                int c = kk + (lane >> 4) * 8;
                ldm4(ah[i], &sAh[r * LDSW + c]);
                ldm4(al[i], &sAl[r * LDSW + c]);
            }
#pragma unroll
            for (int jj = 0; jj < 2; jj++) {
                int r = wn + jj * 16 + ((lane >> 4) << 3) + (lane & 7);
                int c = kk + ((lane >> 3) & 1) * 8;
                unsigned tmp[4];
                ldm4(tmp, &sWh[r * LDSW + c]);
                bh[2 * jj][0] = tmp[0]; bh[2 * jj][1] = tmp[1];
                bh[2 * jj + 1][0] = tmp[2]; bh[2 * jj + 1][1] = tmp[3];
                ldm4(tmp, &sWl[r * LDSW + c]);
                bl[2 * jj][0] = tmp[0]; bl[2 * jj][1] = tmp[1];
                bl[2 * jj + 1][0] = tmp[2]; bl[2 * jj + 1][1] = tmp[3];
            }
#pragma unroll
            for (int i = 0; i < 2; i++)
#pragma unroll
                for (int j = 0; j < 4; j++) {
                    mma_bf16(acc[i][j], ah[i], bh[j]);
                    mma_bf16(acc[i][j], ah[i], bl[j]);
                    mma_bf16(acc[i][j], al[i], bh[j]);
                }
        }
        __syncthreads();
    }

    // ---- epilogue ----
    const int g = lane >> 2, tg = lane & 3;
#pragma unroll
    for (int i = 0; i < 2; i++) {
#pragma unroll
        for (int j = 0; j < 4; j++) {
            int c0 = bn + wn + j * 8 + tg * 2;
#pragma unroll
            for (int h = 0; h < 2; h++) {
                int r = bm + wm + i * 16 + g + h * 8;
                float v0 = acc[i][j][h * 2 + 0];
                float v1 = acc[i][j][h * 2 + 1];
                if (MODE == M_RELU_BIAS) {
                    v0 = fmaxf(v0 + bias[c0], 0.f);
                    v1 = fmaxf(v1 + bias[c0 + 1], 0.f);
                } else if (MODE == M_ADD_BIAS) {
                    v0 += bias[c0];
                    v1 += bias[c0 + 1];
                } else if (MODE == M_TANH_ADDC) {
                    v0 = tanhf(v0 + Cadd[(size_t)r * HH + c0]);
                    v1 = tanhf(v1 + Cadd[(size_t)r * HH + c0 + 1]);
                } else { // M_TANH_BIAS
                    v0 = tanhf(v0 + bias[c0]);
                    v1 = tanhf(v1 + bias[c0 + 1]);
                }
                const size_t idx = (size_t)r * HH + c0;
                if (OUT_SPLIT) {
                    bf16 h0 = __float2bfloat16_rn(v0);
                    bf16 h1 = __float2bfloat16_rn(v1);
                    bf16 l0 = __float2bfloat16_rn(v0 - __bfloat162float(h0));
                    bf16 l1 = __float2bfloat16_rn(v1 - __bfloat162float(h1));
                    __nv_bfloat162 ph = __halves2bfloat162(h0, h1);
                    __nv_bfloat162 pl = __halves2bfloat162(l0, l1);
                    *(unsigned*)&Oh[idx] = *(unsigned*)&ph;
                    *(unsigned*)&Ol[idx] = *(unsigned*)&pl;
                } else {
                    Cout[idx]     = v0;
                    Cout[idx + 1] = v1;
                }
            }
        }
    }
}

// Batched probs for ALL steps: row = (t, b). out[t*BB+b] = sigmoid(hx_t[b,:]·Wa + ba)
__global__ __launch_bounds__(256) void prob_all_kernel(
    const float* __restrict__ Wa, const float* __restrict__ ba,
    float* __restrict__ out)
{
    const int warp = threadIdx.x >> 5, lane = threadIdx.x & 31;
    const long long gr = (long long)blockIdx.x * 8 + warp;  // 0 .. TT*BB-1
    // slot t+1 holds hx after step t
    const bf16* hh = g_hxh + (size_t)BB * HH + (size_t)gr * HH;
    const bf16* hl = g_hxl + (size_t)BB * HH + (size_t)gr * HH;
    float s = 0.f;
#pragma unroll 8
    for (int k = lane; k < HH; k += 32)
        s = fmaf(__bfloat162float(hh[k]) + __bfloat162float(hl[k]), Wa[k], s);
#pragma unroll
    for (int o = 16; o; o >>= 1) s += __shfl_xor_sync(0xffffffffu, s, o);
    if (lane == 0) out[gr] = 1.f / (1.f + expf(-(s + ba[0])));
}

// final hx (fp32) = hi + lo of slot TT
__global__ void final_hx_kernel(float* __restrict__ out)
{
    int i = blockIdx.x * blockDim.x + threadIdx.x;
    const size_t base = (size_t)TT * BB * HH;
    if (i < BB * HH)
        out[i] = __bfloat162float(g_hxh[base + i]) + __bfloat162float(g_hxl[base + i]);
}

// ---------------- launch ----------------
extern "C" void kernel_launch(void* const* d_in, const int* in_sizes, int n_in,
                              void* d_out, int out_size)
{
    const float* inputs = (const float*)d_in[0];
    const float* W1  = (const float*)d_in[1];
    const float* b1  = (const float*)d_in[2];
    const float* W2  = (const float*)d_in[3];
    const float* b2  = (const float*)d_in[4];
    const float* Wih = (const float*)d_in[5];
    const float* Whh = (const float*)d_in[6];
    const float* bih = (const float*)d_in[7];
    const float* bhh = (const float*)d_in[8];
    const float* Wa  = (const float*)d_in[9];
    const float* ba  = (const float*)d_in[10];
    float* out = (float*)d_out;

    float *u, *biasv;
    bf16 *Ih, *Il, *x1h, *x1l;
    bf16 *W1h, *W1l, *W2h, *W2l, *Wihh, *Wihl, *Whhh, *Whhl, *Wsh, *Wsl;
    bf16 *hxh, *hxl;
    cudaGetSymbolAddress((void**)&u,     g_u);
    cudaGetSymbolAddress((void**)&biasv, g_bias);
    cudaGetSymbolAddress((void**)&Ih,   g_Ih);   cudaGetSymbolAddress((void**)&Il,   g_Il);
    cudaGetSymbolAddress((void**)&x1h,  g_x1h);  cudaGetSymbolAddress((void**)&x1l,  g_x1l);
    cudaGetSymbolAddress((void**)&W1h,  g_W1h);  cudaGetSymbolAddress((void**)&W1l,  g_W1l);
    cudaGetSymbolAddress((void**)&W2h,  g_W2h);  cudaGetSymbolAddress((void**)&W2l,  g_W2l);
    cudaGetSymbolAddress((void**)&Wihh, g_Wihh); cudaGetSymbolAddress((void**)&Wihl, g_Wihl);
    cudaGetSymbolAddress((void**)&Whhh, g_Whhh); cudaGetSymbolAddress((void**)&Whhl, g_Whhl);
    cudaGetSymbolAddress((void**)&Wsh,  g_Wsh);  cudaGetSymbolAddress((void**)&Wsl,  g_Wsl);
    cudaGetSymbolAddress((void**)&hxh,  g_hxh);  cudaGetSymbolAddress((void**)&hxl,  g_hxl);

    const size_t SL = (size_t)BB * HH;  // slot stride

    // prep: splits
    split_kernel<<<(BB * FEA + 255) / 256, 256>>>(inputs, Ih, Il, BB * FEA);
    split_kernel<<<(HH * FEA + 255) / 256, 256>>>(W1, W1h, W1l, HH * FEA);
    split_kernel<<<(HH * HH + 255) / 256, 256>>>(W2, W2h, W2l, HH * HH);
    split_kernel<<<(HH * HH + 255) / 256, 256>>>(Wih, Wihh, Wihl, HH * HH);
    split_kernel<<<(HH * HH + 255) / 256, 256>>>(Whh, Whhh, Whhl, HH * HH);
    sumsplit_kernel<<<(HH * HH + 255) / 256, 256>>>(Wih, Whh, Wsh, Wsl, bih, bhh, HH * HH);

    dim3 grid(HH / BN, BB / BM);  // (16, 8)

    // low_fc: x1 = relu(inputs@W1^T + b1) ; xlow = relu(x1@W2^T + b2) -> hx slot 0
    gemm_tc<M_RELU_BIAS, 1><<<grid, 256>>>(Ih, Il, W1h, W1l, (const float*)0, b1,
                                           (float*)0, x1h, x1l, FEA);
    gemm_tc<M_RELU_BIAS, 1><<<grid, 256>>>(x1h, x1l, W2h, W2l, (const float*)0, b2,
                                           (float*)0, hxh, hxl, HH);

    // u = x_low @ Wih^T + (bih + bhh)   (fp32 out)
    gemm_tc<M_ADD_BIAS, 0><<<grid, 256>>>(hxh, hxl, Wihh, Wihl, (const float*)0, biasv,
                                          u, (bf16*)0, (bf16*)0, HH);

    for (int t = 0; t < TT; t++) {
        bf16* ah = hxh + (size_t)t * SL;
        bf16* al = hxl + (size_t)t * SL;
        bf16* oh = hxh + (size_t)(t + 1) * SL;
        bf16* ol = hxl + (size_t)(t + 1) * SL;
        if ((t % GAP) == 0) {
            gemm_tc<M_TANH_ADDC, 1><<<grid, 256>>>(ah, al, Whhh, Whhl, u, (const float*)0,
                                                   (float*)0, oh, ol, HH);
        } else {
            gemm_tc<M_TANH_BIAS, 1><<<grid, 256>>>(ah, al, Wsh, Wsl, (const float*)0, biasv,
                                                   (float*)0, oh, ol, HH);
        }
    }

    // all probs in one launch, then final hx
    prob_all_kernel<<<(TT * BB) / 8, 256>>>(Wa, ba, out);
    final_hx_kernel<<<(BB * HH + 255) / 256, 256>>>(out + (size_t)TT * BB);
}

// round 10
// speedup vs baseline: 3.2612x; 1.1479x over previous
#include <cuda_runtime.h>
#include <cuda_bf16.h>
#include <stdint.h>
#include <math.h>

#define BB 1024
#define FEA 4096
#define HH 1024
#define TT 64
#define GAP 16

#define BM 128
#define BN 64
#define BK 64
#define LDSW 72          // 64 K-elems + 8 pad; 144B rows -> conflict-free ldmatrix
#define NSTAGE 3

// smem layout (bf16 elems)
#define A_STG (BM * LDSW)            // 9216
#define W_STG (BN * LDSW)            // 4608
#define OFF_AH 0
#define OFF_AL (NSTAGE * A_STG)      // 27648
#define OFF_WH (2 * NSTAGE * A_STG)  // 55296
#define OFF_WL (OFF_WH + NSTAGE * W_STG)  // 69120
#define SMEM_ELEMS (OFF_WL + NSTAGE * W_STG)   // 82944
#define SMEM_BYTES (SMEM_ELEMS * 2)            // 165888

typedef __nv_bfloat16 bf16;

// ---------------- scratch (device globals; no allocation allowed) ----------------
__device__ float g_u[BB * HH];
__device__ float g_bias[HH];

__device__ bf16 g_Ih[BB * FEA],  g_Il[BB * FEA];
__device__ bf16 g_x1h[BB * HH],  g_x1l[BB * HH];
__device__ bf16 g_W1h[HH * FEA], g_W1l[HH * FEA];
__device__ bf16 g_W2h[HH * HH],  g_W2l[HH * HH];
__device__ bf16 g_Wihh[HH * HH], g_Wihl[HH * HH];
__device__ bf16 g_Whhh[HH * HH], g_Whhl[HH * HH];
__device__ bf16 g_Wsh[HH * HH],  g_Wsl[HH * HH];

// hx history, split: slot 0 = x_low, slot t+1 = hx after step t
__device__ bf16 g_hxh[(TT + 1) * (size_t)BB * HH];
__device__ bf16 g_hxl[(TT + 1) * (size_t)BB * HH];

#define M_RELU_BIAS 0
#define M_ADD_BIAS  1
#define M_TANH_ADDC 2
#define M_TANH_BIAS 3

// ---------------- PTX helpers ----------------
__device__ __forceinline__ unsigned smem_u32(const void* p) {
    unsigned addr;
    asm("{ .reg .u64 tmp; cvta.to.shared.u64 tmp, %1; cvt.u32.u64 %0, tmp; }"
        : "=r"(addr) : "l"(p));
    return addr;
}

__device__ __forceinline__ void ldm4(unsigned* r, const bf16* p) {
    unsigned a = smem_u32(p);
    asm volatile("ldmatrix.sync.aligned.m8n8.x4.shared.b16 {%0,%1,%2,%3}, [%4];"
                 : "=r"(r[0]), "=r"(r[1]), "=r"(r[2]), "=r"(r[3]) : "r"(a));
}

__device__ __forceinline__ void mma_bf16(float* c, const unsigned* a, const unsigned* b) {
    asm volatile("mma.sync.aligned.m16n8k16.row.col.f32.bf16.bf16.f32 "
                 "{%0,%1,%2,%3},{%4,%5,%6,%7},{%8,%9},{%0,%1,%2,%3};"
                 : "+f"(c[0]), "+f"(c[1]), "+f"(c[2]), "+f"(c[3])
                 : "r"(a[0]), "r"(a[1]), "r"(a[2]), "r"(a[3]), "r"(b[0]), "r"(b[1]));
}

__device__ __forceinline__ void cp16(unsigned dst, const void* src) {
    asm volatile("cp.async.cg.shared.global [%0], [%1], 16;"
                 :: "r"(dst), "l"(src) : "memory");
}

// ---------------- prep kernels ----------------
__global__ void split_kernel(const float* __restrict__ src, bf16* __restrict__ hi,
                             bf16* __restrict__ lo, int n)
{
    int i = blockIdx.x * blockDim.x + threadIdx.x;
    if (i < n) {
        float x = src[i];
        bf16 h = __float2bfloat16_rn(x);
        hi[i] = h;
        lo[i] = __float2bfloat16_rn(x - __bfloat162float(h));
    }
}

__global__ void sumsplit_kernel(const float* __restrict__ a, const float* __restrict__ b,
                                bf16* __restrict__ hi, bf16* __restrict__ lo,
                                const float* __restrict__ bih, const float* __restrict__ bhh,
                                int n)
{
    int i = blockIdx.x * blockDim.x + threadIdx.x;
    if (i < n) {
        float x = a[i] + b[i];
        bf16 h = __float2bfloat16_rn(x);
        hi[i] = h;
        lo[i] = __float2bfloat16_rn(x - __bfloat162float(h));
    }
    if (i < HH) g_bias[i] = bih[i] + bhh[i];
}

// ---------------- async stage issue: one BK=64 chunk into ring stage s ------------
__device__ __forceinline__ void issue_stage(
    unsigned sb, const bf16* __restrict__ Ah, const bf16* __restrict__ Al,
    const bf16* __restrict__ Wh, const bf16* __restrict__ Wl,
    int bm, int bn, int K, int k0, int s, int tid)
{
    const unsigned aH = sb + (OFF_AH + s * A_STG) * 2;
    const unsigned aL = sb + (OFF_AL + s * A_STG) * 2;
    const unsigned wH = sb + (OFF_WH + s * W_STG) * 2;
    const unsigned wL = sb + (OFF_WL + s * W_STG) * 2;
#pragma unroll
    for (int i = 0; i < 4; i++) {               // A: 128 rows x 8 x 16B chunks
        const int idx = i * 256 + tid;
        const int r = idx >> 3, ch = idx & 7;
        const unsigned off = (unsigned)(r * 144 + ch * 16);
        const size_t gs = (size_t)(bm + r) * K + k0 + ch * 8;
        cp16(aH + off, Ah + gs);
        cp16(aL + off, Al + gs);
    }
#pragma unroll
    for (int i = 0; i < 2; i++) {               // W: 64 rows x 8 x 16B chunks
        const int idx = i * 256 + tid;
        const int r = idx >> 3, ch = idx & 7;
        const unsigned off = (unsigned)(r * 144 + ch * 16);
        const size_t gs = (size_t)(bn + r) * K + k0 + ch * 8;
        cp16(wH + off, Wh + gs);
        cp16(wL + off, Wl + gs);
    }
    asm volatile("cp.async.commit_group;" ::: "memory");
}

// ---------------- pipelined tensor-core GEMM ----------------
// C[M,1024] = (Ah+Al)[M,K] @ (Wh+Wl)[1024,K]^T, epilogue MODE, fp32 or split out.
// BM=128, BN=64, BK=64, 3-stage cp.async ring. 256 threads (8 warps 4x2).
template <int MODE, int OUT_SPLIT>
__global__ __launch_bounds__(256) void gemm_cp(
    const bf16* __restrict__ Ah, const bf16* __restrict__ Al,
    const bf16* __restrict__ Wh, const bf16* __restrict__ Wl,
    const float* __restrict__ Cadd, const float* __restrict__ bias,
    float* __restrict__ Cout, bf16* __restrict__ Oh, bf16* __restrict__ Ol,
    int K)
{
    extern __shared__ bf16 sm[];
    const unsigned sb = smem_u32(sm);
    const int tid = threadIdx.x;
    const int lane = tid & 31, wid = tid >> 5;
    const int bm = blockIdx.y * BM, bn = blockIdx.x * BN;
    const int wm = (wid >> 1) * 32;
    const int wn = (wid & 1) * 32;
    const int nch = K / BK;

    float acc[2][4][4];
#pragma unroll
    for (int i = 0; i < 2; i++)
#pragma unroll
        for (int j = 0; j < 4; j++)
#pragma unroll
            for (int q = 0; q < 4; q++) acc[i][j][q] = 0.f;

    issue_stage(sb, Ah, Al, Wh, Wl, bm, bn, K, 0, 0, tid);
    issue_stage(sb, Ah, Al, Wh, Wl, bm, bn, K, BK, 1, tid);

    int s = 0;
    for (int c = 0; c < nch; c++) {
        __syncthreads();   // all warps done with mma(c-1) -> safe to overwrite its buffer
        if (c + 2 < nch)
            issue_stage(sb, Ah, Al, Wh, Wl, bm, bn, K, (c + 2) * BK, (c + 2) % NSTAGE, tid);
        const int rem = nch - 1 - c;
        if (rem >= 2)      asm volatile("cp.async.wait_group 2;" ::: "memory");
        else if (rem == 1) asm volatile("cp.async.wait_group 1;" ::: "memory");
        else               asm volatile("cp.async.wait_group 0;" ::: "memory");
        __syncthreads();   // stage c visible to all threads

        const bf16* pAh = sm + OFF_AH + s * A_STG;
        const bf16* pAl = sm + OFF_AL + s * A_STG;
        const bf16* pWh = sm + OFF_WH + s * W_STG;
        const bf16* pWl = sm + OFF_WL + s * W_STG;
        s++; if (s == NSTAGE) s = 0;

#pragma unroll
        for (int kk = 0; kk < BK; kk += 16) {
            unsigned ah[2][4], al[2][4], bh[4][2], bl[4][2];
#pragma unroll
            for (int i = 0; i < 2; i++) {
                const int r = wm + i * 16 + (lane & 15);
                const int cc = kk + (lane >> 4) * 8;
                ldm4(ah[i], pAh + r * LDSW + cc);
                ldm4(al[i], pAl + r * LDSW + cc);
            }
#pragma unroll
            for (int jj = 0; jj < 2; jj++) {
                const int r = wn + jj * 16 + ((lane >> 4) << 3) + (lane & 7);
                const int cc = kk + ((lane >> 3) & 1) * 8;
                unsigned tmp[4];
                ldm4(tmp, pWh + r * LDSW + cc);
                bh[2 * jj][0] = tmp[0]; bh[2 * jj][1] = tmp[1];
                bh[2 * jj + 1][0] = tmp[2]; bh[2 * jj + 1][1] = tmp[3];
                ldm4(tmp, pWl + r * LDSW + cc);
                bl[2 * jj][0] = tmp[0]; bl[2 * jj][1] = tmp[1];
                bl[2 * jj + 1][0] = tmp[2]; bl[2 * jj + 1][1] = tmp[3];
            }
#pragma unroll
            for (int i = 0; i < 2; i++)
#pragma unroll
                for (int j = 0; j < 4; j++) {
                    mma_bf16(acc[i][j], ah[i], bh[j]);
                    mma_bf16(acc[i][j], ah[i], bl[j]);
                    mma_bf16(acc[i][j], al[i], bh[j]);
                }
        }
    }

    // ---- epilogue (identical mapping to round-7 passing kernel) ----
    const int g = lane >> 2, tg = lane & 3;
#pragma unroll
    for (int i = 0; i < 2; i++) {
#pragma unroll
        for (int j = 0; j < 4; j++) {
            const int c0 = bn + wn + j * 8 + tg * 2;
#pragma unroll
            for (int h = 0; h < 2; h++) {
                const int r = bm + wm + i * 16 + g + h * 8;
                float v0 = acc[i][j][h * 2 + 0];
                float v1 = acc[i][j][h * 2 + 1];
                if (MODE == M_RELU_BIAS) {
                    v0 = fmaxf(v0 + bias[c0], 0.f);
                    v1 = fmaxf(v1 + bias[c0 + 1], 0.f);
                } else if (MODE == M_ADD_BIAS) {
                    v0 += bias[c0];
                    v1 += bias[c0 + 1];
                } else if (MODE == M_TANH_ADDC) {
                    v0 = tanhf(v0 + Cadd[(size_t)r * HH + c0]);
                    v1 = tanhf(v1 + Cadd[(size_t)r * HH + c0 + 1]);
                } else { // M_TANH_BIAS
                    v0 = tanhf(v0 + bias[c0]);
                    v1 = tanhf(v1 + bias[c0 + 1]);
                }
                const size_t idx = (size_t)r * HH + c0;
                if (OUT_SPLIT) {
                    bf16 h0 = __float2bfloat16_rn(v0);
                    bf16 h1 = __float2bfloat16_rn(v1);
                    bf16 l0 = __float2bfloat16_rn(v0 - __bfloat162float(h0));
                    bf16 l1 = __float2bfloat16_rn(v1 - __bfloat162float(h1));
                    __nv_bfloat162 ph = __halves2bfloat162(h0, h1);
                    __nv_bfloat162 pl = __halves2bfloat162(l0, l1);
                    *(unsigned*)&Oh[idx] = *(unsigned*)&ph;
                    *(unsigned*)&Ol[idx] = *(unsigned*)&pl;
                } else {
                    Cout[idx]     = v0;
                    Cout[idx + 1] = v1;
                }
            }
        }
    }
}

// ---------------- batched probs + final hx ----------------
__global__ __launch_bounds__(256) void prob_all_kernel(
    const float* __restrict__ Wa, const float* __restrict__ ba,
    float* __restrict__ out)
{
    const int warp = threadIdx.x >> 5, lane = threadIdx.x & 31;
    const long long gr = (long long)blockIdx.x * 8 + warp;
    const bf16* hh = g_hxh + (size_t)BB * HH + (size_t)gr * HH;
    const bf16* hl = g_hxl + (size_t)BB * HH + (size_t)gr * HH;
    float s = 0.f;
#pragma unroll 8
    for (int k = lane; k < HH; k += 32)
        s = fmaf(__bfloat162float(hh[k]) + __bfloat162float(hl[k]), Wa[k], s);
#pragma unroll
    for (int o = 16; o; o >>= 1) s += __shfl_xor_sync(0xffffffffu, s, o);
    if (lane == 0) out[gr] = 1.f / (1.f + expf(-(s + ba[0])));
}

__global__ void final_hx_kernel(float* __restrict__ out)
{
    int i = blockIdx.x * blockDim.x + threadIdx.x;
    const size_t base = (size_t)TT * BB * HH;
    if (i < BB * HH)
        out[i] = __bfloat162float(g_hxh[base + i]) + __bfloat162float(g_hxl[base + i]);
}

// ---------------- launch ----------------
extern "C" void kernel_launch(void* const* d_in, const int* in_sizes, int n_in,
                              void* d_out, int out_size)
{
    const float* inputs = (const float*)d_in[0];
    const float* W1  = (const float*)d_in[1];
    const float* b1  = (const float*)d_in[2];
    const float* W2  = (const float*)d_in[3];
    const float* b2  = (const float*)d_in[4];
    const float* Wih = (const float*)d_in[5];
    const float* Whh = (const float*)d_in[6];
    const float* bih = (const float*)d_in[7];
    const float* bhh = (const float*)d_in[8];
    const float* Wa  = (const float*)d_in[9];
    const float* ba  = (const float*)d_in[10];
    float* out = (float*)d_out;

    float *u, *biasv;
    bf16 *Ih, *Il, *x1h, *x1l;
    bf16 *W1h, *W1l, *W2h, *W2l, *Wihh, *Wihl, *Whhh, *Whhl, *Wsh, *Wsl;
    bf16 *hxh, *hxl;
    cudaGetSymbolAddress((void**)&u,     g_u);
    cudaGetSymbolAddress((void**)&biasv, g_bias);
    cudaGetSymbolAddress((void**)&Ih,   g_Ih);   cudaGetSymbolAddress((void**)&Il,   g_Il);
    cudaGetSymbolAddress((void**)&x1h,  g_x1h);  cudaGetSymbolAddress((void**)&x1l,  g_x1l);
    cudaGetSymbolAddress((void**)&W1h,  g_W1h);  cudaGetSymbolAddress((void**)&W1l,  g_W1l);
    cudaGetSymbolAddress((void**)&W2h,  g_W2h);  cudaGetSymbolAddress((void**)&W2l,  g_W2l);
    cudaGetSymbolAddress((void**)&Wihh, g_Wihh); cudaGetSymbolAddress((void**)&Wihl, g_Wihl);
    cudaGetSymbolAddress((void**)&Whhh, g_Whhh); cudaGetSymbolAddress((void**)&Whhl, g_Whhl);
    cudaGetSymbolAddress((void**)&Wsh,  g_Wsh);  cudaGetSymbolAddress((void**)&Wsl,  g_Wsl);
    cudaGetSymbolAddress((void**)&hxh,  g_hxh);  cudaGetSymbolAddress((void**)&hxl,  g_hxl);

    cudaFuncSetAttribute(gemm_cp<M_RELU_BIAS, 1>,
                         cudaFuncAttributeMaxDynamicSharedMemorySize, SMEM_BYTES);
    cudaFuncSetAttribute(gemm_cp<M_ADD_BIAS, 0>,
                         cudaFuncAttributeMaxDynamicSharedMemorySize, SMEM_BYTES);
    cudaFuncSetAttribute(gemm_cp<M_TANH_ADDC, 1>,
                         cudaFuncAttributeMaxDynamicSharedMemorySize, SMEM_BYTES);
    cudaFuncSetAttribute(gemm_cp<M_TANH_BIAS, 1>,
                         cudaFuncAttributeMaxDynamicSharedMemorySize, SMEM_BYTES);

    const size_t SL = (size_t)BB * HH;

    // prep: splits
    split_kernel<<<(BB * FEA + 255) / 256, 256>>>(inputs, Ih, Il, BB * FEA);
    split_kernel<<<(HH * FEA + 255) / 256, 256>>>(W1, W1h, W1l, HH * FEA);
    split_kernel<<<(HH * HH + 255) / 256, 256>>>(W2, W2h, W2l, HH * HH);
    split_kernel<<<(HH * HH + 255) / 256, 256>>>(Wih, Wihh, Wihl, HH * HH);
    split_kernel<<<(HH * HH + 255) / 256, 256>>>(Whh, Whhh, Whhl, HH * HH);
    sumsplit_kernel<<<(HH * HH + 255) / 256, 256>>>(Wih, Whh, Wsh, Wsl, bih, bhh, HH * HH);

    dim3 grid(HH / BN, BB / BM);  // (16, 8)

    // low_fc
    gemm_cp<M_RELU_BIAS, 1><<<grid, 256, SMEM_BYTES>>>(Ih, Il, W1h, W1l,
        (const float*)0, b1, (float*)0, x1h, x1l, FEA);
    gemm_cp<M_RELU_BIAS, 1><<<grid, 256, SMEM_BYTES>>>(x1h, x1l, W2h, W2l,
        (const float*)0, b2, (float*)0, hxh, hxl, HH);

    // u = x_low @ Wih^T + (bih + bhh)
    gemm_cp<M_ADD_BIAS, 0><<<grid, 256, SMEM_BYTES>>>(hxh, hxl, Wihh, Wihl,
        (const float*)0, biasv, u, (bf16*)0, (bf16*)0, HH);

    for (int t = 0; t < TT; t++) {
        bf16* ah = hxh + (size_t)t * SL;
        bf16* al = hxl + (size_t)t * SL;
        bf16* oh = hxh + (size_t)(t + 1) * SL;
        bf16* ol = hxl + (size_t)(t + 1) * SL;
        if ((t % GAP) == 0) {
            gemm_cp<M_TANH_ADDC, 1><<<grid, 256, SMEM_BYTES>>>(ah, al, Whhh, Whhl,
                u, (const float*)0, (float*)0, oh, ol, HH);
        } else {
            gemm_cp<M_TANH_BIAS, 1><<<grid, 256, SMEM_BYTES>>>(ah, al, Wsh, Wsl,
                (const float*)0, biasv, (float*)0, oh, ol, HH);
        }
    }

    prob_all_kernel<<<(TT * BB) / 8, 256>>>(Wa, ba, out);
    final_hx_kernel<<<(BB * HH + 255) / 256, 256>>>(out + (size_t)TT * BB);
}